// round 14
// baseline (speedup 1.0000x reference)
#include <cuda_runtime.h>

// Problem dims (fixed by the reference setup_inputs)
#define B_    256
#define F_    300
#define JC_   1600
#define NC_   60
#define J4_   (JC_ / 4)    // 400 float4 per frame
#define CHUNK 30           // frames per pooling tile
#define NCH   (F_ / CHUNK) // 10 chunks
#define NTILE (B_ * NCH)   // 2560 pooling tiles
#define NQ    (NC_ / 4)    // 15 n-quads
#define BTILE 16           // batch rows per fc task
#define BT_N  (B_ / BTILE) // 16 batch tiles
#define NFCT  (NQ * BT_N)  // 240 fc tasks
#define THREADS 400

// Pooled (un-normalized) feature sums [B, JC] — 1.6 MB
__device__ float    g_pooled[(size_t)B_ * JC_];
// Per-batch chunk-arrival counters (memset to 0 each launch)
__device__ unsigned g_done[B_];

__device__ __forceinline__ unsigned ld_acquire_gpu(const unsigned* p) {
    unsigned v;
    asm volatile("ld.global.acquire.gpu.u32 %0, [%1];" : "=r"(v) : "l"(p) : "memory");
    return v;
}

// ---------------------------------------------------------------------------
// Warp-specialized fused kernel. grid = NFCT + NTILE = 2800, block = 400.
//  bid <  240 : FC role. Prefetch W[:,4q..4q+3] into smem at once (overlaps
//               the pool stream), spin per warp on g_done, then the proven
//               R12 dot (coalesced pooled-row LDG x LDS.128 of sW).
//  bid >= 240 : pool role (R12 body: unroll-8 __ldcs + red.global.add.v4),
//               then fence + atomicAdd arrival on g_done[b].
// One kernel, one stream -> trivially graph-capturable; overlap comes from
// concurrent residency, not streams.
// ---------------------------------------------------------------------------
__global__ __launch_bounds__(THREADS, 3) void fused_kernel(
    const float* __restrict__ x,       // [B, F, JC]
    const int*   __restrict__ lengths, // [B]
    const float* __restrict__ W,       // [JC, NC] row-major
    const float* __restrict__ bias,    // [NC]
    float*       __restrict__ out)     // [B, NC]
{
    __shared__ float4 sW[JC_];         // 25.6 KB (FC role only)

    const int bid = blockIdx.x;
    const int t   = threadIdx.x;

    if (bid < NFCT) {
        // ================= FC role =================
        const int q  = bid % NQ;              // 0..14
        const int b0 = (bid / NQ) * BTILE;    // batch tile base

        // W slice -> smem NOW (overlaps with pooling on other SMs)
        const float4* __restrict__ W4 = reinterpret_cast<const float4*>(W);
#pragma unroll
        for (int j = t; j < JC_; j += THREADS)
            sW[j] = W4[(size_t)j * NQ + q];
        __syncthreads();

        if (t < 256) {
            const int w = t >> 5;             // 0..7
            const int l = t & 31;
            const int bA = b0 + w;
            const int bB = b0 + w + 8;

            // spin until both batches fully pooled
            while (ld_acquire_gpu(&g_done[bA]) < (unsigned)NCH) __nanosleep(128);
            while (ld_acquire_gpu(&g_done[bB]) < (unsigned)NCH) __nanosleep(128);
            __syncwarp();

            const int lenA = lengths[bA];
            const int lenB = lengths[bB];
            const float* __restrict__ srcA = (lenA <= 1)
                ? (x + (size_t)bA * F_ * JC_) : (g_pooled + (size_t)bA * JC_);
            const float* __restrict__ srcB = (lenB <= 1)
                ? (x + (size_t)bB * F_ * JC_) : (g_pooled + (size_t)bB * JC_);
            const float invA = (lenA <= 1) ? 1.0f : 1.0f / (float)lenA;
            const float invB = (lenB <= 1) ? 1.0f : 1.0f / (float)lenB;

            float4 a0 = make_float4(0.f, 0.f, 0.f, 0.f);
            float4 a1 = a0;
#pragma unroll 10
            for (int k = 0; k < JC_ / 32; k++) {   // 50 iterations, batched
                const int j = k * 32 + l;
                const float pA = srcA[j];          // coalesced 128B warp load
                const float pB = srcB[j];
                const float4 wv = sW[j];           // conflict-free LDS.128
                a0.x += pA * wv.x; a0.y += pA * wv.y;
                a0.z += pA * wv.z; a0.w += pA * wv.w;
                a1.x += pB * wv.x; a1.y += pB * wv.y;
                a1.z += pB * wv.z; a1.w += pB * wv.w;
            }
#pragma unroll
            for (int off = 16; off > 0; off >>= 1) {
                a0.x += __shfl_xor_sync(0xFFFFFFFF, a0.x, off);
                a0.y += __shfl_xor_sync(0xFFFFFFFF, a0.y, off);
                a0.z += __shfl_xor_sync(0xFFFFFFFF, a0.z, off);
                a0.w += __shfl_xor_sync(0xFFFFFFFF, a0.w, off);
                a1.x += __shfl_xor_sync(0xFFFFFFFF, a1.x, off);
                a1.y += __shfl_xor_sync(0xFFFFFFFF, a1.y, off);
                a1.z += __shfl_xor_sync(0xFFFFFFFF, a1.z, off);
                a1.w += __shfl_xor_sync(0xFFFFFFFF, a1.w, off);
            }
            if (l == 0) {
                const int n = 4 * q;
                const float c0 = bias[n + 0], c1 = bias[n + 1];
                const float c2 = bias[n + 2], c3 = bias[n + 3];
                float* oA = out + (size_t)bA * NC_ + n;
                oA[0] = a0.x * invA + c0; oA[1] = a0.y * invA + c1;
                oA[2] = a0.z * invA + c2; oA[3] = a0.w * invA + c3;
                float* oB = out + (size_t)bB * NC_ + n;
                oB[0] = a1.x * invB + c0; oB[1] = a1.y * invB + c1;
                oB[2] = a1.z * invB + c2; oB[3] = a1.w * invB + c3;
            }
        }
        return;
    }

    // ================= Pool role =================
    const int tile = bid - NFCT;
    const int b = tile / NCH;          // b-major: batches complete progressively
    const int c = tile - b * NCH;
    const int len = lengths[b];
    const int f0 = c * CHUNK;

    if (f0 < len) {
        const int f1 = min(f0 + CHUNK, len);
        const float4* __restrict__ xb =
            reinterpret_cast<const float4*>(x + (size_t)b * F_ * JC_);
        const int j4 = t;

        float ax = 0.f, ay = 0.f, az = 0.f, aw = 0.f;
        int f = f0;
        for (; f + 8 <= f1; f += 8) {
            float4 v0 = __ldcs(&xb[(size_t)(f + 0) * J4_ + j4]);
            float4 v1 = __ldcs(&xb[(size_t)(f + 1) * J4_ + j4]);
            float4 v2 = __ldcs(&xb[(size_t)(f + 2) * J4_ + j4]);
            float4 v3 = __ldcs(&xb[(size_t)(f + 3) * J4_ + j4]);
            float4 v4 = __ldcs(&xb[(size_t)(f + 4) * J4_ + j4]);
            float4 v5 = __ldcs(&xb[(size_t)(f + 5) * J4_ + j4]);
            float4 v6 = __ldcs(&xb[(size_t)(f + 6) * J4_ + j4]);
            float4 v7 = __ldcs(&xb[(size_t)(f + 7) * J4_ + j4]);
            ax += (v0.x + v1.x) + (v2.x + v3.x) + ((v4.x + v5.x) + (v6.x + v7.x));
            ay += (v0.y + v1.y) + (v2.y + v3.y) + ((v4.y + v5.y) + (v6.y + v7.y));
            az += (v0.z + v1.z) + (v2.z + v3.z) + ((v4.z + v5.z) + (v6.z + v7.z));
            aw += (v0.w + v1.w) + (v2.w + v3.w) + ((v4.w + v5.w) + (v6.w + v7.w));
        }
        for (; f < f1; f++) {
            float4 v = __ldcs(&xb[(size_t)f * J4_ + j4]);
            ax += v.x; ay += v.y; az += v.z; aw += v.w;
        }
        float* dst = g_pooled + (size_t)b * JC_ + j4 * 4;
        asm volatile("red.global.add.v4.f32 [%0], {%1, %2, %3, %4};"
                     :: "l"(dst), "f"(ax), "f"(ay), "f"(az), "f"(aw)
                     : "memory");
    }

    // arrival: publish reds, then count (every pool block arrives)
    __threadfence();
    __syncthreads();
    if (t == 0) atomicAdd(&g_done[b], 1u);
}

extern "C" void kernel_launch(void* const* d_in, const int* in_sizes, int n_in,
                              void* d_out, int out_size)
{
    const float* x       = (const float*)d_in[0];
    const int*   lengths = (const int*)  d_in[1];
    const float* W       = (const float*)d_in[2];
    const float* bias    = (const float*)d_in[3];
    float*       out     = (float*)d_out;

    // zero accumulator + counters (graph-capturable memset nodes)
    void* pooled_ptr = nullptr;
    cudaGetSymbolAddress(&pooled_ptr, g_pooled);
    cudaMemsetAsync(pooled_ptr, 0, sizeof(float) * (size_t)B_ * JC_);
    void* done_ptr = nullptr;
    cudaGetSymbolAddress(&done_ptr, g_done);
    cudaMemsetAsync(done_ptr, 0, sizeof(unsigned) * B_);

    fused_kernel<<<NFCT + NTILE, THREADS>>>(x, lengths, W, bias, out);
}

// round 15
// speedup vs baseline: 1.1559x; 1.1559x over previous
#include <cuda_runtime.h>

// Problem dims (fixed by the reference setup_inputs)
#define B_    256
#define F_    300
#define JC_   1600
#define NC_   60
#define J4_   (JC_ / 4)    // 400 float4 per frame
#define CHUNK 50           // frames per pooling tile (was 30)
#define NCH   (F_ / CHUNK) // 6 chunks
#define NQ    (NC_ / 4)    // 15 n-quads
#define BTILE 16           // batch rows per fc block
#define BT_N  (B_ / BTILE) // 16 batch tiles

// Pooled (un-normalized) feature sums [B, JC] — 1.6 MB, built via red.global
__device__ float g_pooled[(size_t)B_ * JC_];

// ---------------------------------------------------------------------------
// Kernel 1: chunk pooling. grid = (B, NCH=6), block = 400, occ 3.
// CHUNK=50 cuts red.global lane count 40% (LTS atomic-ALU occupancy was a
// hidden serial cost) and wave count 5.8 -> 3.5, while per-block work stays
// bounded at 320 KB.
// ---------------------------------------------------------------------------
__global__ __launch_bounds__(400, 3) void pool_part_kernel(
    const float* __restrict__ x,       // [B, F, JC]
    const int*   __restrict__ lengths) // [B]
{
    const int b  = blockIdx.x;
    const int c  = blockIdx.y;
    const int j4 = threadIdx.x;

    const int len = __ldg(&lengths[b]);
    const int f0  = c * CHUNK;
    if (f0 >= len) return;
    const int f1  = min(f0 + CHUNK, len);

    const float4* __restrict__ xb =
        reinterpret_cast<const float4*>(x + (size_t)b * F_ * JC_);

    float ax = 0.f, ay = 0.f, az = 0.f, aw = 0.f;
    int f = f0;
    // unroll by 8: up to 8 independent LDG.128 in flight per thread
    for (; f + 8 <= f1; f += 8) {
        float4 v0 = __ldcs(&xb[(size_t)(f + 0) * J4_ + j4]);
        float4 v1 = __ldcs(&xb[(size_t)(f + 1) * J4_ + j4]);
        float4 v2 = __ldcs(&xb[(size_t)(f + 2) * J4_ + j4]);
        float4 v3 = __ldcs(&xb[(size_t)(f + 3) * J4_ + j4]);
        float4 v4 = __ldcs(&xb[(size_t)(f + 4) * J4_ + j4]);
        float4 v5 = __ldcs(&xb[(size_t)(f + 5) * J4_ + j4]);
        float4 v6 = __ldcs(&xb[(size_t)(f + 6) * J4_ + j4]);
        float4 v7 = __ldcs(&xb[(size_t)(f + 7) * J4_ + j4]);
        ax += (v0.x + v1.x) + (v2.x + v3.x) + ((v4.x + v5.x) + (v6.x + v7.x));
        ay += (v0.y + v1.y) + (v2.y + v3.y) + ((v4.y + v5.y) + (v6.y + v7.y));
        az += (v0.z + v1.z) + (v2.z + v3.z) + ((v4.z + v5.z) + (v6.z + v7.z));
        aw += (v0.w + v1.w) + (v2.w + v3.w) + ((v4.w + v5.w) + (v6.w + v7.w));
    }
    for (; f < f1; f++) {
        float4 v = __ldcs(&xb[(size_t)f * J4_ + j4]);
        ax += v.x; ay += v.y; az += v.z; aw += v.w;
    }
    float* dst = g_pooled + (size_t)b * JC_ + j4 * 4;
    asm volatile("red.global.add.v4.f32 [%0], {%1, %2, %3, %4};"
                 :: "l"(dst), "f"(ax), "f"(ay), "f"(az), "f"(aw)
                 : "memory");
}

// ---------------------------------------------------------------------------
// Kernel 2: FC, W-slice in shared + register headroom (proven R12, 9.8 us).
// grid = (NQ=15, BT_N=16) = 240 blocks, block = 256 (8 warps), regs<=255.
// ---------------------------------------------------------------------------
__global__ __launch_bounds__(256, 1) void fc_kernel(
    const float* __restrict__ x,       // [B, F, JC] (len<=1 edge case)
    const int*   __restrict__ lengths, // [B]
    const float* __restrict__ W,       // [JC, NC] row-major
    const float* __restrict__ bias,    // [NC]
    float*       __restrict__ out)     // [B, NC]
{
    __shared__ float4 sW[JC_];         // 25.6 KB: W[:, 4q..4q+3]

    const int q  = blockIdx.x;         // 0..14
    const int b0 = blockIdx.y * BTILE; // batch tile base
    const int t  = threadIdx.x;
    const int w  = t >> 5;             // 0..7
    const int l  = t & 31;

    // ---- load W slice into shared (independent 16B gathers) ----
    const float4* __restrict__ W4 = reinterpret_cast<const float4*>(W); // [JC][15]
#pragma unroll
    for (int j = t; j < JC_; j += 256)
        sW[j] = W4[(size_t)j * NQ + q];
    __syncthreads();

    // ---- two rows per warp (8 FMA chains), deep unroll ----
    const int bA = b0 + w;
    const int bB = b0 + w + 8;
    const int lenA = lengths[bA];
    const int lenB = lengths[bB];
    const float* __restrict__ srcA =
        (lenA <= 1) ? (x + (size_t)bA * F_ * JC_) : (g_pooled + (size_t)bA * JC_);
    const float* __restrict__ srcB =
        (lenB <= 1) ? (x + (size_t)bB * F_ * JC_) : (g_pooled + (size_t)bB * JC_);
    const float invA = (lenA <= 1) ? 1.0f : 1.0f / (float)lenA;
    const float invB = (lenB <= 1) ? 1.0f : 1.0f / (float)lenB;

    float4 a0 = make_float4(0.f, 0.f, 0.f, 0.f);
    float4 a1 = a0;

#pragma unroll 10
    for (int k = 0; k < JC_ / 32; k++) {   // 50 iterations, 10 batched
        const int j = k * 32 + l;
        const float pA = srcA[j];          // coalesced 128B warp load
        const float pB = srcB[j];
        const float4 wv = sW[j];           // conflict-free LDS.128
        a0.x += pA * wv.x; a0.y += pA * wv.y; a0.z += pA * wv.z; a0.w += pA * wv.w;
        a1.x += pB * wv.x; a1.y += pB * wv.y; a1.z += pB * wv.z; a1.w += pB * wv.w;
    }

    // warp-shuffle reduce all 8 components
#pragma unroll
    for (int off = 16; off > 0; off >>= 1) {
        a0.x += __shfl_xor_sync(0xFFFFFFFF, a0.x, off);
        a0.y += __shfl_xor_sync(0xFFFFFFFF, a0.y, off);
        a0.z += __shfl_xor_sync(0xFFFFFFFF, a0.z, off);
        a0.w += __shfl_xor_sync(0xFFFFFFFF, a0.w, off);
        a1.x += __shfl_xor_sync(0xFFFFFFFF, a1.x, off);
        a1.y += __shfl_xor_sync(0xFFFFFFFF, a1.y, off);
        a1.z += __shfl_xor_sync(0xFFFFFFFF, a1.z, off);
        a1.w += __shfl_xor_sync(0xFFFFFFFF, a1.w, off);
    }

    if (l == 0) {
        const int n = 4 * q;
        const float c0 = bias[n + 0], c1 = bias[n + 1];
        const float c2 = bias[n + 2], c3 = bias[n + 3];
        float* oA = out + (size_t)bA * NC_ + n;
        oA[0] = a0.x * invA + c0; oA[1] = a0.y * invA + c1;
        oA[2] = a0.z * invA + c2; oA[3] = a0.w * invA + c3;
        float* oB = out + (size_t)bB * NC_ + n;
        oB[0] = a1.x * invB + c0; oB[1] = a1.y * invB + c1;
        oB[2] = a1.z * invB + c2; oB[3] = a1.w * invB + c3;
    }
}

extern "C" void kernel_launch(void* const* d_in, const int* in_sizes, int n_in,
                              void* d_out, int out_size)
{
    const float* x       = (const float*)d_in[0];
    const int*   lengths = (const int*)  d_in[1];
    const float* W       = (const float*)d_in[2];
    const float* bias    = (const float*)d_in[3];
    float*       out     = (float*)d_out;

    // zero the accumulator (graph-capturable memset node; no allocation)
    void* pooled_ptr = nullptr;
    cudaGetSymbolAddress(&pooled_ptr, g_pooled);
    cudaMemsetAsync(pooled_ptr, 0, sizeof(float) * (size_t)B_ * JC_);

    dim3 grid_pool(B_, NCH);
    pool_part_kernel<<<grid_pool, 400>>>(x, lengths);
    dim3 grid_fc(NQ, BT_N);
    fc_kernel<<<grid_fc, 256>>>(x, lengths, W, bias, out);
}